// round 1
// baseline (speedup 1.0000x reference)
#include <cuda_runtime.h>
#include <math.h>

// Problem constants
#define BS      2
#define SEQ     2048
#define DMODEL  1024
#define NH      16
#define DHEAD   64
#define MROWS   (BS*SEQ)     // 4096
#define NCOLS   1024         // H*DH == D
#define KDIM    1024
#define ATT_SCALE 0.125f     // 64^-0.5

// Scratch (device globals: allocation-free, graph-capturable)
__device__ float g_Q[MROWS*NCOLS];
__device__ float g_K[MROWS*NCOLS];
__device__ float g_V[MROWS*NCOLS];
__device__ float g_O[MROWS*NCOLS];

// ---------------------------------------------------------------------------
// SGEMM: C[M,N] = A[M,K] @ W[K,N] (+ optional bias). M=4096, N=K=1024.
// 64x64 tile, BK=16, 256 threads, 4x4 register blocking.
// ---------------------------------------------------------------------------
__global__ __launch_bounds__(256)
void gemm64_kernel(const float* __restrict__ A, const float* __restrict__ W,
                   const float* __restrict__ bias, float* __restrict__ C) {
    __shared__ float As[16][68];   // A tile transposed: As[k][m]
    __shared__ float Bsm[16][68];  // B tile: Bsm[k][n]

    const int tid = threadIdx.x;
    const int ty = tid >> 4;       // 0..15
    const int tx = tid & 15;       // 0..15
    const int rowBase = blockIdx.y * 64;
    const int colBase = blockIdx.x * 64;

    float acc[4][4] = {};

    for (int k0 = 0; k0 < KDIM; k0 += 16) {
        // Load A tile (64 rows x 16 k) as 256 float4s
        {
            const int r  = tid >> 2;   // 0..63
            const int c4 = tid & 3;    // 0..3
            float4 v = *reinterpret_cast<const float4*>(
                &A[(size_t)(rowBase + r) * KDIM + k0 + c4 * 4]);
            As[c4*4+0][r] = v.x;
            As[c4*4+1][r] = v.y;
            As[c4*4+2][r] = v.z;
            As[c4*4+3][r] = v.w;
        }
        // Load W tile (16 k x 64 n) as 256 float4s
        {
            const int r  = tid >> 4;   // 0..15
            const int c4 = tid & 15;   // 0..15
            float4 v = *reinterpret_cast<const float4*>(
                &W[(size_t)(k0 + r) * NCOLS + colBase + c4 * 4]);
            *reinterpret_cast<float4*>(&Bsm[r][c4*4]) = v;
        }
        __syncthreads();

#pragma unroll
        for (int kk = 0; kk < 16; kk++) {
            float4 a4 = *reinterpret_cast<const float4*>(&As[kk][ty*4]);
            float4 b4 = *reinterpret_cast<const float4*>(&Bsm[kk][tx*4]);
            float av[4] = {a4.x, a4.y, a4.z, a4.w};
            float bv[4] = {b4.x, b4.y, b4.z, b4.w};
#pragma unroll
            for (int i = 0; i < 4; i++)
#pragma unroll
                for (int j = 0; j < 4; j++)
                    acc[i][j] = fmaf(av[i], bv[j], acc[i][j]);
        }
        __syncthreads();
    }

#pragma unroll
    for (int i = 0; i < 4; i++) {
        const int r = rowBase + ty*4 + i;
#pragma unroll
        for (int j = 0; j < 4; j++) {
            const int c = colBase + tx*4 + j;
            float v = acc[i][j];
            if (bias) v += bias[c];
            C[(size_t)r * NCOLS + c] = v;
        }
    }
}

// ---------------------------------------------------------------------------
// Flash attention: one CTA per (b, h, 64-query tile). 256 threads.
// Quad-per-row layout: row = tid/4, q = tid%4.
//   Score phase : thread's 16 cols are interleaved  c_j = q + 4*j
//   PV phase    : thread's 16 dims are blocked      d   = q*16 .. q*16+15
// Dynamic smem: Qs/Ks/Vs/Ps each [64][68] floats -> 69632 B.
// ---------------------------------------------------------------------------
#define TILE 64
#define LDT  68

__global__ __launch_bounds__(256)
void attn_kernel(const float* __restrict__ Q, const float* __restrict__ K,
                 const float* __restrict__ V, float* __restrict__ O) {
    extern __shared__ float sm[];
    float* Qs = sm;                    // [64][68]
    float* Ks = Qs + TILE*LDT;
    float* Vs = Ks + TILE*LDT;
    float* Ps = Vs + TILE*LDT;

    const int tid = threadIdx.x;
    const int bh  = blockIdx.y;            // 0..31
    const int b   = bh / NH;
    const int h   = bh % NH;
    const int qBase = blockIdx.x * TILE;

    const int row = tid >> 2;              // 0..63
    const int q   = tid & 3;               // 0..3

    // Load Q tile: 64x64 floats = 1024 float4s, 4 per thread
    {
        const size_t gbase = ((size_t)(b * SEQ + qBase)) * NCOLS + h * DHEAD;
#pragma unroll
        for (int i = 0; i < 4; i++) {
            int f  = tid + i * 256;
            int r  = f >> 4;       // 0..63
            int c4 = f & 15;       // 0..15
            float4 v = *reinterpret_cast<const float4*>(&Q[gbase + (size_t)r * NCOLS + c4*4]);
            *reinterpret_cast<float4*>(&Qs[r*LDT + c4*4]) = v;
        }
    }

    float mrow = -INFINITY;
    float lrow = 0.0f;
    float o[16];
#pragma unroll
    for (int j = 0; j < 16; j++) o[j] = 0.0f;

    for (int kBase = 0; kBase < SEQ; kBase += TILE) {
        // Load K,V tiles
        {
            const size_t gbase = ((size_t)(b * SEQ + kBase)) * NCOLS + h * DHEAD;
#pragma unroll
            for (int i = 0; i < 4; i++) {
                int f  = tid + i * 256;
                int r  = f >> 4;
                int c4 = f & 15;
                float4 kv = *reinterpret_cast<const float4*>(&K[gbase + (size_t)r * NCOLS + c4*4]);
                float4 vv = *reinterpret_cast<const float4*>(&V[gbase + (size_t)r * NCOLS + c4*4]);
                *reinterpret_cast<float4*>(&Ks[r*LDT + c4*4]) = kv;
                *reinterpret_cast<float4*>(&Vs[r*LDT + c4*4]) = vv;
            }
        }
        __syncthreads();

        // Scores: s[j] = Q[row] . K[q+4j], j=0..15
        float s[16];
#pragma unroll
        for (int j = 0; j < 16; j++) s[j] = 0.0f;
#pragma unroll 4
        for (int d4 = 0; d4 < 16; d4++) {
            float4 qv = *reinterpret_cast<const float4*>(&Qs[row*LDT + d4*4]);
#pragma unroll
            for (int j = 0; j < 16; j++) {
                float4 kv = *reinterpret_cast<const float4*>(&Ks[(q + 4*j)*LDT + d4*4]);
                s[j] = fmaf(qv.x, kv.x, s[j]);
                s[j] = fmaf(qv.y, kv.y, s[j]);
                s[j] = fmaf(qv.z, kv.z, s[j]);
                s[j] = fmaf(qv.w, kv.w, s[j]);
            }
        }
#pragma unroll
        for (int j = 0; j < 16; j++) s[j] *= ATT_SCALE;

        // Online softmax update
        float tmax = s[0];
#pragma unroll
        for (int j = 1; j < 16; j++) tmax = fmaxf(tmax, s[j]);
        tmax = fmaxf(tmax, __shfl_xor_sync(0xffffffffu, tmax, 1));
        tmax = fmaxf(tmax, __shfl_xor_sync(0xffffffffu, tmax, 2));

        float newm  = fmaxf(mrow, tmax);
        float alpha = __expf(mrow - newm);
        float psum = 0.0f;
#pragma unroll
        for (int j = 0; j < 16; j++) {
            float p = __expf(s[j] - newm);
            s[j] = p;
            psum += p;
        }
        psum += __shfl_xor_sync(0xffffffffu, psum, 1);
        psum += __shfl_xor_sync(0xffffffffu, psum, 2);
        lrow = lrow * alpha + psum;
        mrow = newm;
#pragma unroll
        for (int j = 0; j < 16; j++) o[j] *= alpha;

        // Share P via smem
#pragma unroll
        for (int j = 0; j < 16; j++) Ps[row*LDT + q + 4*j] = s[j];
        __syncthreads();

        // PV: o[d] += sum_c P[row][c] * V[c][d], d in [q*16, q*16+16)
#pragma unroll 8
        for (int c = 0; c < TILE; c++) {
            float p = Ps[row*LDT + c];
#pragma unroll
            for (int jj = 0; jj < 4; jj++) {
                float4 vv = *reinterpret_cast<const float4*>(&Vs[c*LDT + q*16 + jj*4]);
                o[jj*4+0] = fmaf(p, vv.x, o[jj*4+0]);
                o[jj*4+1] = fmaf(p, vv.y, o[jj*4+1]);
                o[jj*4+2] = fmaf(p, vv.z, o[jj*4+2]);
                o[jj*4+3] = fmaf(p, vv.w, o[jj*4+3]);
            }
        }
        __syncthreads();
    }

    // Normalize and write: O[b, qBase+row, h*64 + q*16 + jj]
    const float inv = 1.0f / lrow;
    const size_t obase = ((size_t)(b * SEQ + qBase + row)) * NCOLS + h * DHEAD + q * 16;
#pragma unroll
    for (int jj = 0; jj < 16; jj++)
        O[obase + jj] = o[jj] * inv;
}

// ---------------------------------------------------------------------------
// Launch
// Inputs (metadata order): x, Wq, Wk, Wv, Wo, bo
// ---------------------------------------------------------------------------
extern "C" void kernel_launch(void* const* d_in, const int* in_sizes, int n_in,
                              void* d_out, int out_size) {
    const float* x  = (const float*)d_in[0];
    const float* Wq = (const float*)d_in[1];
    const float* Wk = (const float*)d_in[2];
    const float* Wv = (const float*)d_in[3];
    const float* Wo = (const float*)d_in[4];
    const float* bo = (const float*)d_in[5];
    float* out = (float*)d_out;

    float *gQ, *gK, *gV, *gO;
    cudaGetSymbolAddress((void**)&gQ, g_Q);
    cudaGetSymbolAddress((void**)&gK, g_K);
    cudaGetSymbolAddress((void**)&gV, g_V);
    cudaGetSymbolAddress((void**)&gO, g_O);

    const int ATTN_SMEM = 4 * TILE * LDT * (int)sizeof(float);  // 69632
    cudaFuncSetAttribute(attn_kernel, cudaFuncAttributeMaxDynamicSharedMemorySize, ATTN_SMEM);

    dim3 ggrid(NCOLS / 64, MROWS / 64);  // (16, 64)
    dim3 gblock(256);

    // QKV projections
    gemm64_kernel<<<ggrid, gblock>>>(x, Wq, nullptr, gQ);
    gemm64_kernel<<<ggrid, gblock>>>(x, Wk, nullptr, gK);
    gemm64_kernel<<<ggrid, gblock>>>(x, Wv, nullptr, gV);

    // Attention
    dim3 agrid(SEQ / TILE, BS * NH);     // (32, 32)
    attn_kernel<<<agrid, dim3(256), ATTN_SMEM>>>(gQ, gK, gV, gO);

    // Output projection + bias
    gemm64_kernel<<<ggrid, gblock>>>(gO, Wo, bo, out);
}

// round 3
// speedup vs baseline: 1.1563x; 1.1563x over previous
#include <cuda_runtime.h>
#include <cuda_bf16.h>
#include <math.h>
#include <stdint.h>

// Problem constants
#define BS      2
#define SEQ     2048
#define DMODEL  1024
#define NH      16
#define DHEAD   64
#define MROWS   (BS*SEQ)     // 4096
#define NCOLS   1024
#define KDIM    1024
#define ATT_SCALE 0.125f

// ---------------------------------------------------------------------------
// Scratch (device globals: allocation-free, graph-capturable)
// ---------------------------------------------------------------------------
__device__ float g_Q[MROWS*NCOLS];
__device__ float g_K[MROWS*NCOLS];
__device__ float g_V[MROWS*NCOLS];
__device__ float g_O[MROWS*NCOLS];
__device__ __nv_bfloat16 g_ah[MROWS*KDIM];   // A hi (x or O)
__device__ __nv_bfloat16 g_al[MROWS*KDIM];   // A lo
__device__ __nv_bfloat16 g_bth[NCOLS*KDIM];  // W^T hi  [n][k]
__device__ __nv_bfloat16 g_btl[NCOLS*KDIM];  // W^T lo

// ---------------------------------------------------------------------------
// PTX helpers (sm_80/90 baseline features only: mma.sync / ldmatrix / cp.async)
// ---------------------------------------------------------------------------
__device__ __forceinline__ uint32_t smem_u32(const void* p) {
    uint32_t a;
    asm("{ .reg .u64 t; cvta.to.shared.u64 t, %1; cvt.u32.u64 %0, t; }" : "=r"(a) : "l"(p));
    return a;
}
#define LDSM_X4(r0, r1, r2, r3, addr) \
    asm volatile("ldmatrix.sync.aligned.m8n8.x4.shared.b16 {%0,%1,%2,%3}, [%4];" \
                 : "=r"(r0), "=r"(r1), "=r"(r2), "=r"(r3) : "r"(addr))
#define CP_ASYNC16(dst, src) \
    asm volatile("cp.async.cg.shared.global [%0], [%1], 16;" :: "r"(dst), "l"(src))
#define CP_COMMIT() asm volatile("cp.async.commit_group;" ::: "memory")
#define CP_WAIT(n)  asm volatile("cp.async.wait_group %0;" :: "n"(n) : "memory")

__device__ __forceinline__ void mma_bf16(float* c, const uint32_t* a, const uint32_t* b) {
    asm volatile(
        "mma.sync.aligned.m16n8k16.row.col.f32.bf16.bf16.f32 "
        "{%0,%1,%2,%3}, {%4,%5,%6,%7}, {%8,%9}, {%0,%1,%2,%3};"
        : "+f"(c[0]), "+f"(c[1]), "+f"(c[2]), "+f"(c[3])
        : "r"(a[0]), "r"(a[1]), "r"(a[2]), "r"(a[3]), "r"(b[0]), "r"(b[1]));
}

// ---------------------------------------------------------------------------
// fp32 -> bf16 hi/lo split (elementwise, vectorized by 4)
// ---------------------------------------------------------------------------
__global__ __launch_bounds__(256)
void split_kernel(const float* __restrict__ in, __nv_bfloat16* __restrict__ hi,
                  __nv_bfloat16* __restrict__ lo, int n4) {
    int i = blockIdx.x * 256 + threadIdx.x;
    if (i >= n4) return;
    float4 v = reinterpret_cast<const float4*>(in)[i];
    ushort4 h, l;
    __nv_bfloat16 t;
    t = __float2bfloat16(v.x); h.x = __bfloat16_as_ushort(t);
    l.x = __bfloat16_as_ushort(__float2bfloat16(v.x - __bfloat162float(t)));
    t = __float2bfloat16(v.y); h.y = __bfloat16_as_ushort(t);
    l.y = __bfloat16_as_ushort(__float2bfloat16(v.y - __bfloat162float(t)));
    t = __float2bfloat16(v.z); h.z = __bfloat16_as_ushort(t);
    l.z = __bfloat16_as_ushort(__float2bfloat16(v.z - __bfloat162float(t)));
    t = __float2bfloat16(v.w); h.w = __bfloat16_as_ushort(t);
    l.w = __bfloat16_as_ushort(__float2bfloat16(v.w - __bfloat162float(t)));
    reinterpret_cast<ushort4*>(hi)[i] = h;
    reinterpret_cast<ushort4*>(lo)[i] = l;
}

// ---------------------------------------------------------------------------
// W[K,N] -> W^T hi/lo bf16 [N,K] (tiled transpose + split)
// ---------------------------------------------------------------------------
__global__ __launch_bounds__(256)
void tsplit_kernel(const float* __restrict__ W, __nv_bfloat16* __restrict__ th,
                   __nv_bfloat16* __restrict__ tl) {
    __shared__ float t[32][33];
    const int tx = threadIdx.x, ty = threadIdx.y;  // (32, 8)
    const int n0 = blockIdx.x * 32, k0 = blockIdx.y * 32;
#pragma unroll
    for (int i = 0; i < 4; i++)
        t[ty + 8*i][tx] = W[(size_t)(k0 + ty + 8*i) * NCOLS + n0 + tx];
    __syncthreads();
#pragma unroll
    for (int i = 0; i < 4; i++) {
        float v = t[tx][ty + 8*i];
        size_t o = (size_t)(n0 + ty + 8*i) * KDIM + k0 + tx;
        __nv_bfloat16 h = __float2bfloat16(v);
        th[o] = h;
        tl[o] = __float2bfloat16(v - __bfloat162float(h));
    }
}

// ---------------------------------------------------------------------------
// Warp-MMA GEMM: C[M,N] = (Ah+Al)[M,K] @ (Bh+Bl)^T  (B stored [N,K])
// CTA 128x128, 8 warps (2m x 4n), warp tile 64x32, BK=32, cp.async 2-stage.
// Per k16 step: acc += Ah*Bh + Ah*Bl + Al*Bh  (AlBl dropped, ~2^-18 rel).
// ---------------------------------------------------------------------------
#define BK     32
#define SKS    40                       // padded bf16 stride; 80B rows (16B-aligned)
#define TILE_B (128*SKS*2)              // 10240 B per tile
#define STAGE_B (4*TILE_B)              // Ah, Al, Bh, Bl
#define GSM_TOTAL (2*STAGE_B)           // 81920 B
#define NCHUNK (KDIM/BK)                // 32

__device__ __forceinline__ void issue_chunk(int tid, uint32_t sb, int stage,
                                            const __nv_bfloat16* const* srcs, int kc) {
    const uint32_t base = sb + stage * STAGE_B;
#pragma unroll
    for (int t = 0; t < 4; t++) {
        const __nv_bfloat16* s = srcs[t] + kc * BK;
#pragma unroll
        for (int i = 0; i < 2; i++) {
            int f = tid + i * 256;
            int r = f >> 2;            // 0..127
            int c = f & 3;             // 0..3 (16B units)
            CP_ASYNC16(base + t * TILE_B + (uint32_t)(r * SKS + c * 8) * 2,
                       s + (size_t)r * KDIM + c * 8);
        }
    }
    CP_COMMIT();
}

__global__ __launch_bounds__(256, 1)
void gemm_mma(const __nv_bfloat16* __restrict__ Ah, const __nv_bfloat16* __restrict__ Al,
              const __nv_bfloat16* __restrict__ Bh, const __nv_bfloat16* __restrict__ Bl,
              const float* __restrict__ bias, float* __restrict__ C) {
    extern __shared__ char smem[];
    const uint32_t sb = smem_u32(smem);
    const int tid = threadIdx.x;
    const int wid = tid >> 5;
    const int lane = tid & 31;
    const int wm = wid >> 2;            // 0..1
    const int wn = wid & 3;             // 0..3
    const int n0 = blockIdx.x * 128;
    const int m0 = blockIdx.y * 128;

    const __nv_bfloat16* srcs[4] = {
        Ah + (size_t)m0 * KDIM, Al + (size_t)m0 * KDIM,
        Bh + (size_t)n0 * KDIM, Bl + (size_t)n0 * KDIM
    };

    float acc[4][4][4];                 // [mi][ni][frag]
#pragma unroll
    for (int i = 0; i < 4; i++)
#pragma unroll
        for (int j = 0; j < 4; j++)
#pragma unroll
            for (int f = 0; f < 4; f++) acc[i][j][f] = 0.0f;

    // ldmatrix lane addressing precompute
    const int sub = lane >> 3;          // 0..3
    const int l8  = lane & 7;           // 0..7
    // A: matrix sub -> row +=(sub&1)*8, col +=(sub>>1)*8
    const int a_row = (sub & 1) * 8 + l8;
    const int a_col = (sub >> 1) * 8;
    // B: matrix sub -> col += sub*8
    const int b_row = l8;
    const int b_col = sub * 8;

    issue_chunk(tid, sb, 0, srcs, 0);

    for (int kc = 0; kc < NCHUNK; kc++) {
        const int cur = kc & 1;
        if (kc + 1 < NCHUNK) {
            issue_chunk(tid, sb, (kc + 1) & 1, srcs, kc + 1);
            CP_WAIT(1);
        } else {
            CP_WAIT(0);
        }
        __syncthreads();

        const uint32_t st = sb + cur * STAGE_B;
        const uint32_t sAh = st + 0 * TILE_B;
        const uint32_t sAl = st + 1 * TILE_B;
        const uint32_t sBh = st + 2 * TILE_B;
        const uint32_t sBl = st + 3 * TILE_B;

        // B fragments for the whole chunk: [ni][4] regs, regs {0,1}=k0..15, {2,3}=k16..31
        uint32_t bh[4][4], bl[4][4];
#pragma unroll
        for (int ni = 0; ni < 4; ni++) {
            uint32_t off = (uint32_t)((wn * 32 + ni * 8 + b_row) * SKS + b_col) * 2;
            LDSM_X4(bh[ni][0], bh[ni][1], bh[ni][2], bh[ni][3], sBh + off);
            LDSM_X4(bl[ni][0], bl[ni][1], bl[ni][2], bl[ni][3], sBl + off);
        }

#pragma unroll
        for (int ks = 0; ks < 2; ks++) {
            uint32_t ah[4][4], al[4][4];
#pragma unroll
            for (int mi = 0; mi < 4; mi++) {
                uint32_t off = (uint32_t)((wm * 64 + mi * 16 + a_row) * SKS + ks * 16 + a_col) * 2;
                LDSM_X4(ah[mi][0], ah[mi][1], ah[mi][2], ah[mi][3], sAh + off);
                LDSM_X4(al[mi][0], al[mi][1], al[mi][2], al[mi][3], sAl + off);
            }
#pragma unroll
            for (int mi = 0; mi < 4; mi++) {
#pragma unroll
                for (int ni = 0; ni < 4; ni++) {
                    uint32_t bfh[2] = { bh[ni][ks*2], bh[ni][ks*2+1] };
                    uint32_t bfl[2] = { bl[ni][ks*2], bl[ni][ks*2+1] };
                    mma_bf16(acc[mi][ni], ah[mi], bfh);
                    mma_bf16(acc[mi][ni], ah[mi], bfl);
                    mma_bf16(acc[mi][ni], al[mi], bfh);
                }
            }
        }
        __syncthreads();
    }

    // Epilogue: frag (mi,ni): rows l/4, l/4+8; cols (l%4)*2, +1
    const int r0 = m0 + wm * 64 + (lane >> 2);
    const int c0 = n0 + wn * 32 + (lane & 3) * 2;
#pragma unroll
    for (int mi = 0; mi < 4; mi++) {
#pragma unroll
        for (int ni = 0; ni < 4; ni++) {
            int rr = r0 + mi * 16;
            int cc = c0 + ni * 8;
            float2 v0 = { acc[mi][ni][0], acc[mi][ni][1] };
            float2 v1 = { acc[mi][ni][2], acc[mi][ni][3] };
            if (bias) {
                v0.x += bias[cc]; v0.y += bias[cc + 1];
                v1.x += bias[cc]; v1.y += bias[cc + 1];
            }
            *reinterpret_cast<float2*>(&C[(size_t)rr * NCOLS + cc]) = v0;
            *reinterpret_cast<float2*>(&C[(size_t)(rr + 8) * NCOLS + cc]) = v1;
        }
    }
}

// ---------------------------------------------------------------------------
// Flash attention (fp32): one CTA per (b, h, 64-query tile). 256 threads.
// ---------------------------------------------------------------------------
#define TILE 64
#define LDT  68

__global__ __launch_bounds__(256)
void attn_kernel(const float* __restrict__ Q, const float* __restrict__ K,
                 const float* __restrict__ V, float* __restrict__ O) {
    extern __shared__ float sm[];
    float* Qs = sm;
    float* Ks = Qs + TILE*LDT;
    float* Vs = Ks + TILE*LDT;
    float* Ps = Vs + TILE*LDT;

    const int tid = threadIdx.x;
    const int bh  = blockIdx.y;
    const int b   = bh / NH;
    const int h   = bh % NH;
    const int qBase = blockIdx.x * TILE;

    const int row = tid >> 2;
    const int q   = tid & 3;

    {
        const size_t gbase = ((size_t)(b * SEQ + qBase)) * NCOLS + h * DHEAD;
#pragma unroll
        for (int i = 0; i < 4; i++) {
            int f  = tid + i * 256;
            int r  = f >> 4;
            int c4 = f & 15;
            float4 v = *reinterpret_cast<const float4*>(&Q[gbase + (size_t)r * NCOLS + c4*4]);
            *reinterpret_cast<float4*>(&Qs[r*LDT + c4*4]) = v;
        }
    }

    float mrow = -INFINITY;
    float lrow = 0.0f;
    float o[16];
#pragma unroll
    for (int j = 0; j < 16; j++) o[j] = 0.0f;

    for (int kBase = 0; kBase < SEQ; kBase += TILE) {
        {
            const size_t gbase = ((size_t)(b * SEQ + kBase)) * NCOLS + h * DHEAD;
#pragma unroll
            for (int i = 0; i < 4; i++) {
                int f  = tid + i * 256;
                int r  = f >> 4;
                int c4 = f & 15;
                float4 kv = *reinterpret_cast<const float4*>(&K[gbase + (size_t)r * NCOLS + c4*4]);
                float4 vv = *reinterpret_cast<const float4*>(&V[gbase + (size_t)r * NCOLS + c4*4]);
                *reinterpret_cast<float4*>(&Ks[r*LDT + c4*4]) = kv;
                *reinterpret_cast<float4*>(&Vs[r*LDT + c4*4]) = vv;
            }
        }
        __syncthreads();

        float s[16];
#pragma unroll
        for (int j = 0; j < 16; j++) s[j] = 0.0f;
#pragma unroll 4
        for (int d4 = 0; d4 < 16; d4++) {
            float4 qv = *reinterpret_cast<const float4*>(&Qs[row*LDT + d4*4]);
#pragma unroll
            for (int j = 0; j < 16; j++) {
                float4 kv = *reinterpret_cast<const float4*>(&Ks[(q + 4*j)*LDT + d4*4]);
                s[j] = fmaf(qv.x, kv.x, s[j]);
                s[j] = fmaf(qv.y, kv.y, s[j]);
                s[j] = fmaf(qv.z, kv.z, s[j]);
                s[j] = fmaf(qv.w, kv.w, s[j]);
            }
        }
#pragma unroll
        for (int j = 0; j < 16; j++) s[j] *= ATT_SCALE;

        float tmax = s[0];
#pragma unroll
        for (int j = 1; j < 16; j++) tmax = fmaxf(tmax, s[j]);
        tmax = fmaxf(tmax, __shfl_xor_sync(0xffffffffu, tmax, 1));
        tmax = fmaxf(tmax, __shfl_xor_sync(0xffffffffu, tmax, 2));

        float newm  = fmaxf(mrow, tmax);
        float alpha = __expf(mrow - newm);
        float psum = 0.0f;
#pragma unroll
        for (int j = 0; j < 16; j++) {
            float p = __expf(s[j] - newm);
            s[j] = p;
            psum += p;
        }
        psum += __shfl_xor_sync(0xffffffffu, psum, 1);
        psum += __shfl_xor_sync(0xffffffffu, psum, 2);
        lrow = lrow * alpha + psum;
        mrow = newm;
#pragma unroll
        for (int j = 0; j < 16; j++) o[j] *= alpha;

#pragma unroll
        for (int j = 0; j < 16; j++) Ps[row*LDT + q + 4*j] = s[j];
        __syncthreads();

#pragma unroll 8
        for (int c = 0; c < TILE; c++) {
            float p = Ps[row*LDT + c];
#pragma unroll
            for (int jj = 0; jj < 4; jj++) {
                float4 vv = *reinterpret_cast<const float4*>(&Vs[c*LDT + q*16 + jj*4]);
                o[jj*4+0] = fmaf(p, vv.x, o[jj*4+0]);
                o[jj*4+1] = fmaf(p, vv.y, o[jj*4+1]);
                o[jj*4+2] = fmaf(p, vv.z, o[jj*4+2]);
                o[jj*4+3] = fmaf(p, vv.w, o[jj*4+3]);
            }
        }
        __syncthreads();
    }

    const float inv = 1.0f / lrow;
    const size_t obase = ((size_t)(b * SEQ + qBase + row)) * NCOLS + h * DHEAD + q * 16;
#pragma unroll
    for (int jj = 0; jj < 16; jj++)
        O[obase + jj] = o[jj] * inv;
}

// ---------------------------------------------------------------------------
// Launch.  Inputs (metadata order): x, Wq, Wk, Wv, Wo, bo
// ---------------------------------------------------------------------------
extern "C" void kernel_launch(void* const* d_in, const int* in_sizes, int n_in,
                              void* d_out, int out_size) {
    const float* x  = (const float*)d_in[0];
    const float* Wq = (const float*)d_in[1];
    const float* Wk = (const float*)d_in[2];
    const float* Wv = (const float*)d_in[3];
    const float* Wo = (const float*)d_in[4];
    const float* bo = (const float*)d_in[5];
    float* out = (float*)d_out;

    float *gQ, *gK, *gV, *gO;
    __nv_bfloat16 *ah, *al, *bth, *btl;
    cudaGetSymbolAddress((void**)&gQ, g_Q);
    cudaGetSymbolAddress((void**)&gK, g_K);
    cudaGetSymbolAddress((void**)&gV, g_V);
    cudaGetSymbolAddress((void**)&gO, g_O);
    cudaGetSymbolAddress((void**)&ah, g_ah);
    cudaGetSymbolAddress((void**)&al, g_al);
    cudaGetSymbolAddress((void**)&bth, g_bth);
    cudaGetSymbolAddress((void**)&btl, g_btl);

    const int ATTN_SMEM = 4 * TILE * LDT * (int)sizeof(float);
    cudaFuncSetAttribute(attn_kernel, cudaFuncAttributeMaxDynamicSharedMemorySize, ATTN_SMEM);
    cudaFuncSetAttribute(gemm_mma, cudaFuncAttributeMaxDynamicSharedMemorySize, GSM_TOTAL);

    const int n4x = MROWS * KDIM / 4;
    dim3 tgrid(NCOLS / 32, KDIM / 32), tblock(32, 8);
    dim3 ggrid(NCOLS / 128, MROWS / 128);   // (8, 32)

    // x -> bf16 hi/lo
    split_kernel<<<(n4x + 255) / 256, 256>>>(x, ah, al, n4x);

    // QKV projections (warp MMA)
    tsplit_kernel<<<tgrid, tblock>>>(Wq, bth, btl);
    gemm_mma<<<ggrid, 256, GSM_TOTAL>>>(ah, al, bth, btl, nullptr, gQ);
    tsplit_kernel<<<tgrid, tblock>>>(Wk, bth, btl);
    gemm_mma<<<ggrid, 256, GSM_TOTAL>>>(ah, al, bth, btl, nullptr, gK);
    tsplit_kernel<<<tgrid, tblock>>>(Wv, bth, btl);
    gemm_mma<<<ggrid, 256, GSM_TOTAL>>>(ah, al, bth, btl, nullptr, gV);

    // Attention (fp32)
    dim3 agrid(SEQ / TILE, BS * NH);
    attn_kernel<<<agrid, 256, ATTN_SMEM>>>(gQ, gK, gV, gO);

    // O -> bf16 hi/lo, output projection + bias
    split_kernel<<<(n4x + 255) / 256, 256>>>(gO, ah, al, n4x);
    tsplit_kernel<<<tgrid, tblock>>>(Wo, bth, btl);
    gemm_mma<<<ggrid, 256, GSM_TOTAL>>>(ah, al, bth, btl, bo, out);
}

// round 4
// speedup vs baseline: 5.0645x; 4.3798x over previous
#include <cuda_runtime.h>
#include <cuda_bf16.h>
#include <math.h>
#include <stdint.h>

// Problem constants
#define BS      2
#define SEQ     2048
#define DMODEL  1024
#define NH      16
#define DHEAD   64
#define MROWS   (BS*SEQ)     // 4096
#define NCOLS   1024
#define KDIM    1024
#define ATT_SCALE 0.125f

// ---------------------------------------------------------------------------
// Scratch (device globals: allocation-free, graph-capturable)
// ---------------------------------------------------------------------------
__device__ __nv_bfloat16 g_ah[MROWS*KDIM];   // x-split / attn-O hi
__device__ __nv_bfloat16 g_al[MROWS*KDIM];   // x-split / attn-O lo
__device__ __nv_bfloat16 g_bth[NCOLS*KDIM];  // W^T hi [n][k]
__device__ __nv_bfloat16 g_btl[NCOLS*KDIM];  // W^T lo
__device__ __nv_bfloat16 g_qh[MROWS*NCOLS];
__device__ __nv_bfloat16 g_ql[MROWS*NCOLS];
__device__ __nv_bfloat16 g_kh[MROWS*NCOLS];
__device__ __nv_bfloat16 g_kl[MROWS*NCOLS];
__device__ __nv_bfloat16 g_vh[MROWS*NCOLS];
__device__ __nv_bfloat16 g_vl[MROWS*NCOLS];

// ---------------------------------------------------------------------------
// PTX helpers (baseline sm_80/90 features only)
// ---------------------------------------------------------------------------
__device__ __forceinline__ uint32_t smem_u32(const void* p) {
    uint32_t a;
    asm("{ .reg .u64 t; cvta.to.shared.u64 t, %1; cvt.u32.u64 %0, t; }" : "=r"(a) : "l"(p));
    return a;
}
#define LDSM_X4(r0, r1, r2, r3, addr) \
    asm volatile("ldmatrix.sync.aligned.m8n8.x4.shared.b16 {%0,%1,%2,%3}, [%4];" \
                 : "=r"(r0), "=r"(r1), "=r"(r2), "=r"(r3) : "r"(addr))
#define LDSM_X4T(r0, r1, r2, r3, addr) \
    asm volatile("ldmatrix.sync.aligned.m8n8.x4.trans.shared.b16 {%0,%1,%2,%3}, [%4];" \
                 : "=r"(r0), "=r"(r1), "=r"(r2), "=r"(r3) : "r"(addr))
#define CP_ASYNC16(dst, src) \
    asm volatile("cp.async.cg.shared.global [%0], [%1], 16;" :: "r"(dst), "l"(src))
#define CP_COMMIT() asm volatile("cp.async.commit_group;" ::: "memory")
#define CP_WAIT(n)  asm volatile("cp.async.wait_group %0;" :: "n"(n) : "memory")

__device__ __forceinline__ void mma_bf16(float* c, const uint32_t* a, const uint32_t* b) {
    asm volatile(
        "mma.sync.aligned.m16n8k16.row.col.f32.bf16.bf16.f32 "
        "{%0,%1,%2,%3}, {%4,%5,%6,%7}, {%8,%9}, {%0,%1,%2,%3};"
        : "+f"(c[0]), "+f"(c[1]), "+f"(c[2]), "+f"(c[3])
        : "r"(a[0]), "r"(a[1]), "r"(a[2]), "r"(a[3]), "r"(b[0]), "r"(b[1]));
}

// split two floats into packed bf16x2 hi + lo residual
__device__ __forceinline__ void split2(float a, float b, uint32_t& h, uint32_t& l) {
    __nv_bfloat16 ha = __float2bfloat16(a), hb = __float2bfloat16(b);
    __nv_bfloat162 hh; hh.x = ha; hh.y = hb;
    h = *reinterpret_cast<uint32_t*>(&hh);
    __nv_bfloat162 ll;
    ll.x = __float2bfloat16(a - __bfloat162float(ha));
    ll.y = __float2bfloat16(b - __bfloat162float(hb));
    l = *reinterpret_cast<uint32_t*>(&ll);
}

// ---------------------------------------------------------------------------
// fp32 -> bf16 hi/lo split (x input)
// ---------------------------------------------------------------------------
__global__ __launch_bounds__(256)
void split_kernel(const float* __restrict__ in, __nv_bfloat16* __restrict__ hi,
                  __nv_bfloat16* __restrict__ lo, int n4) {
    int i = blockIdx.x * 256 + threadIdx.x;
    if (i >= n4) return;
    float4 v = reinterpret_cast<const float4*>(in)[i];
    ushort4 h, l;
    __nv_bfloat16 t;
    t = __float2bfloat16(v.x); h.x = __bfloat16_as_ushort(t);
    l.x = __bfloat16_as_ushort(__float2bfloat16(v.x - __bfloat162float(t)));
    t = __float2bfloat16(v.y); h.y = __bfloat16_as_ushort(t);
    l.y = __bfloat16_as_ushort(__float2bfloat16(v.y - __bfloat162float(t)));
    t = __float2bfloat16(v.z); h.z = __bfloat16_as_ushort(t);
    l.z = __bfloat16_as_ushort(__float2bfloat16(v.z - __bfloat162float(t)));
    t = __float2bfloat16(v.w); h.w = __bfloat16_as_ushort(t);
    l.w = __bfloat16_as_ushort(__float2bfloat16(v.w - __bfloat162float(t)));
    reinterpret_cast<ushort4*>(hi)[i] = h;
    reinterpret_cast<ushort4*>(lo)[i] = l;
}

// ---------------------------------------------------------------------------
// W[K,N] -> W^T hi/lo bf16 [N,K]
// ---------------------------------------------------------------------------
__global__ __launch_bounds__(256)
void tsplit_kernel(const float* __restrict__ W, __nv_bfloat16* __restrict__ th,
                   __nv_bfloat16* __restrict__ tl) {
    __shared__ float t[32][33];
    const int tx = threadIdx.x, ty = threadIdx.y;  // (32, 8)
    const int n0 = blockIdx.x * 32, k0 = blockIdx.y * 32;
#pragma unroll
    for (int i = 0; i < 4; i++)
        t[ty + 8*i][tx] = W[(size_t)(k0 + ty + 8*i) * NCOLS + n0 + tx];
    __syncthreads();
#pragma unroll
    for (int i = 0; i < 4; i++) {
        float v = t[tx][ty + 8*i];
        size_t o = (size_t)(n0 + ty + 8*i) * KDIM + k0 + tx;
        __nv_bfloat16 h = __float2bfloat16(v);
        th[o] = h;
        tl[o] = __float2bfloat16(v - __bfloat162float(h));
    }
}

// ---------------------------------------------------------------------------
// Warp-MMA GEMM: C = (Ah+Al) @ (Bh+Bl)^T.  CTA 128x128, BK=32, 2-stage.
// Epilogue: either fp32 (+bias) to Cf, or bf16 hi/lo split (scaled) to Ch/Cl.
// ---------------------------------------------------------------------------
#define BK     32
#define SKS    40
#define TILE_B (128*SKS*2)
#define STAGE_B (4*TILE_B)
#define GSM_TOTAL (2*STAGE_B)
#define NCHUNK (KDIM/BK)

__device__ __forceinline__ void issue_chunk(int tid, uint32_t sb, int stage,
                                            const __nv_bfloat16* const* srcs, int kc) {
    const uint32_t base = sb + stage * STAGE_B;
#pragma unroll
    for (int t = 0; t < 4; t++) {
        const __nv_bfloat16* s = srcs[t] + kc * BK;
#pragma unroll
        for (int i = 0; i < 2; i++) {
            int f = tid + i * 256;
            int r = f >> 2;
            int c = f & 3;
            CP_ASYNC16(base + t * TILE_B + (uint32_t)(r * SKS + c * 8) * 2,
                       s + (size_t)r * KDIM + c * 8);
        }
    }
    CP_COMMIT();
}

__global__ __launch_bounds__(256, 1)
void gemm_mma(const __nv_bfloat16* __restrict__ Ah, const __nv_bfloat16* __restrict__ Al,
              const __nv_bfloat16* __restrict__ Bh, const __nv_bfloat16* __restrict__ Bl,
              float* __restrict__ Cf, const float* __restrict__ bias,
              __nv_bfloat16* __restrict__ Ch, __nv_bfloat16* __restrict__ Cl,
              float scale) {
    extern __shared__ char smem[];
    const uint32_t sb = smem_u32(smem);
    const int tid = threadIdx.x;
    const int wid = tid >> 5;
    const int lane = tid & 31;
    const int wm = wid >> 2;
    const int wn = wid & 3;
    const int n0 = blockIdx.x * 128;
    const int m0 = blockIdx.y * 128;

    const __nv_bfloat16* srcs[4] = {
        Ah + (size_t)m0 * KDIM, Al + (size_t)m0 * KDIM,
        Bh + (size_t)n0 * KDIM, Bl + (size_t)n0 * KDIM
    };

    float acc[4][4][4];
#pragma unroll
    for (int i = 0; i < 4; i++)
#pragma unroll
        for (int j = 0; j < 4; j++)
#pragma unroll
            for (int f = 0; f < 4; f++) acc[i][j][f] = 0.0f;

    const int sub = lane >> 3;
    const int l8  = lane & 7;
    const int a_row = (sub & 1) * 8 + l8;
    const int a_col = (sub >> 1) * 8;
    const int b_row = l8;
    const int b_col = sub * 8;

    issue_chunk(tid, sb, 0, srcs, 0);

    for (int kc = 0; kc < NCHUNK; kc++) {
        const int cur = kc & 1;
        if (kc + 1 < NCHUNK) {
            issue_chunk(tid, sb, (kc + 1) & 1, srcs, kc + 1);
            CP_WAIT(1);
        } else {
            CP_WAIT(0);
        }
        __syncthreads();

        const uint32_t st = sb + cur * STAGE_B;
        const uint32_t sAh = st + 0 * TILE_B;
        const uint32_t sAl = st + 1 * TILE_B;
        const uint32_t sBh = st + 2 * TILE_B;
        const uint32_t sBl = st + 3 * TILE_B;

        uint32_t bh[4][4], bl[4][4];
#pragma unroll
        for (int ni = 0; ni < 4; ni++) {
            uint32_t off = (uint32_t)((wn * 32 + ni * 8 + b_row) * SKS + b_col) * 2;
            LDSM_X4(bh[ni][0], bh[ni][1], bh[ni][2], bh[ni][3], sBh + off);
            LDSM_X4(bl[ni][0], bl[ni][1], bl[ni][2], bl[ni][3], sBl + off);
        }

#pragma unroll
        for (int ks = 0; ks < 2; ks++) {
            uint32_t ah[4][4], al[4][4];
#pragma unroll
            for (int mi = 0; mi < 4; mi++) {
                uint32_t off = (uint32_t)((wm * 64 + mi * 16 + a_row) * SKS + ks * 16 + a_col) * 2;
                LDSM_X4(ah[mi][0], ah[mi][1], ah[mi][2], ah[mi][3], sAh + off);
                LDSM_X4(al[mi][0], al[mi][1], al[mi][2], al[mi][3], sAl + off);
            }
#pragma unroll
            for (int mi = 0; mi < 4; mi++) {
#pragma unroll
                for (int ni = 0; ni < 4; ni++) {
                    uint32_t bfh[2] = { bh[ni][ks*2], bh[ni][ks*2+1] };
                    uint32_t bfl[2] = { bl[ni][ks*2], bl[ni][ks*2+1] };
                    mma_bf16(acc[mi][ni], ah[mi], bfh);
                    mma_bf16(acc[mi][ni], ah[mi], bfl);
                    mma_bf16(acc[mi][ni], al[mi], bfh);
                }
            }
        }
        __syncthreads();
    }

    const int r0 = m0 + wm * 64 + (lane >> 2);
    const int c0 = n0 + wn * 32 + (lane & 3) * 2;
#pragma unroll
    for (int mi = 0; mi < 4; mi++) {
#pragma unroll
        for (int ni = 0; ni < 4; ni++) {
            int rr = r0 + mi * 16;
            int cc = c0 + ni * 8;
            if (Cf) {
                float2 v0 = { acc[mi][ni][0], acc[mi][ni][1] };
                float2 v1 = { acc[mi][ni][2], acc[mi][ni][3] };
                if (bias) {
                    v0.x += bias[cc]; v0.y += bias[cc + 1];
                    v1.x += bias[cc]; v1.y += bias[cc + 1];
                }
                *reinterpret_cast<float2*>(&Cf[(size_t)rr * NCOLS + cc]) = v0;
                *reinterpret_cast<float2*>(&Cf[(size_t)(rr + 8) * NCOLS + cc]) = v1;
            } else {
                uint32_t h, l;
                split2(acc[mi][ni][0] * scale, acc[mi][ni][1] * scale, h, l);
                *reinterpret_cast<uint32_t*>(&Ch[(size_t)rr * NCOLS + cc]) = h;
                *reinterpret_cast<uint32_t*>(&Cl[(size_t)rr * NCOLS + cc]) = l;
                split2(acc[mi][ni][2] * scale, acc[mi][ni][3] * scale, h, l);
                *reinterpret_cast<uint32_t*>(&Ch[(size_t)(rr + 8) * NCOLS + cc]) = h;
                *reinterpret_cast<uint32_t*>(&Cl[(size_t)(rr + 8) * NCOLS + cc]) = l;
            }
        }
    }
}

// ---------------------------------------------------------------------------
// MMA flash attention. CTA: 128 q-rows x one (b,h). 8 warps, 16 rows each.
// KV chunks of 64, cp.async double-buffered. Hi/lo split on Q,K,V,P.
// Writes O as bf16 hi/lo (input to the final projection GEMM).
// ---------------------------------------------------------------------------
#define SQ      72                    // padded bf16 row stride (144 B)
#define AQ_H    0
#define AQ_L    (128*SQ*2)            // 18432
#define AK_BASE (2*128*SQ*2)          // 36864
#define AV_BASE (AK_BASE + 2*2*64*SQ*2)  // 73728
#define A_STG   (2*64*SQ*2)           // 18432 (hi+lo per stage)
#define A_HALF  (64*SQ*2)             // 9216
#define A_SMEM  (AV_BASE + 2*A_STG)   // 110592
#define NKC     (SEQ/64)              // 32

__device__ __forceinline__ void attn_issue(int tid, uint32_t sb, int stage,
        const __nv_bfloat16* Kh_, const __nv_bfloat16* Kl_,
        const __nv_bfloat16* Vh_, const __nv_bfloat16* Vl_,
        size_t rowbase, int colb) {
    const __nv_bfloat16* srcs[4] = { Kh_, Kl_, Vh_, Vl_ };
    const uint32_t dstb[4] = {
        sb + AK_BASE + stage * A_STG,          sb + AK_BASE + stage * A_STG + A_HALF,
        sb + AV_BASE + stage * A_STG,          sb + AV_BASE + stage * A_STG + A_HALF };
#pragma unroll
    for (int i = 0; i < 8; i++) {
        int u = tid + i * 256;
        int t = u >> 9;
        int r = (u >> 3) & 63;
        int c = u & 7;
        CP_ASYNC16(dstb[t] + (uint32_t)(r * SQ + c * 8) * 2,
                   srcs[t] + (rowbase + r) * NCOLS + colb + c * 8);
    }
    CP_COMMIT();
}

__global__ __launch_bounds__(256, 1)
void attn_mma(const __nv_bfloat16* __restrict__ Qh_, const __nv_bfloat16* __restrict__ Ql_,
              const __nv_bfloat16* __restrict__ Kh_, const __nv_bfloat16* __restrict__ Kl_,
              const __nv_bfloat16* __restrict__ Vh_, const __nv_bfloat16* __restrict__ Vl_,
              __nv_bfloat16* __restrict__ Oh_, __nv_bfloat16* __restrict__ Ol_) {
    extern __shared__ char smem[];
    const uint32_t sb = smem_u32(smem);
    const int tid = threadIdx.x;
    const int w = tid >> 5;
    const int lane = tid & 31;
    const int bh = blockIdx.y;
    const int b = bh >> 4;
    const int h = bh & 15;
    const int q0 = blockIdx.x * 128;
    const size_t qrow = (size_t)b * SEQ + q0;
    const size_t krow0 = (size_t)b * SEQ;
    const int colb = h * DHEAD;

    // Q tile cp.async (group 0)
    {
        const __nv_bfloat16* srcs[2] = { Qh_, Ql_ };
#pragma unroll
        for (int i = 0; i < 8; i++) {
            int u = tid + i * 256;
            int t = u >> 10;
            int r = (u >> 3) & 127;
            int c = u & 7;
            CP_ASYNC16(sb + (t ? AQ_L : AQ_H) + (uint32_t)(r * SQ + c * 8) * 2,
                       srcs[t] + (qrow + r) * NCOLS + colb + c * 8);
        }
        CP_COMMIT();
    }

    const int mi = lane >> 3;
    const int l8 = lane & 7;
    // A (Q): m16 x k16 blocks: row = w*16 + (mi&1)*8 + l8, col = ks*16 + (mi>>1)*8
    const uint32_t a_off = (uint32_t)((w * 16 + (mi & 1) * 8 + l8) * SQ + (mi >> 1) * 8) * 2;
    // B (K): pair p: row = p*16 + (mi>>1)*8 + l8, col = ks*16 + (mi&1)*8
    const uint32_t k_off = (uint32_t)(((mi >> 1) * 8 + l8) * SQ + (mi & 1) * 8) * 2;
    // B (V, trans): row = kk*16 + (mi&1)*8 + l8, col = p*16 + (mi>>1)*8
    const uint32_t v_off = (uint32_t)(((mi & 1) * 8 + l8) * SQ + (mi >> 1) * 8) * 2;

    float m0 = -1e30f, m1 = -1e30f, l0 = 0.0f, l1 = 0.0f;
    float o[8][4];
#pragma unroll
    for (int i = 0; i < 8; i++)
#pragma unroll
        for (int j = 0; j < 4; j++) o[i][j] = 0.0f;

    attn_issue(tid, sb, 0, Kh_, Kl_, Vh_, Vl_, krow0, colb);

    for (int kc = 0; kc < NKC; kc++) {
        const int cur = kc & 1;
        if (kc + 1 < NKC) {
            attn_issue(tid, sb, (kc + 1) & 1, Kh_, Kl_, Vh_, Vl_, krow0 + (kc + 1) * 64, colb);
            CP_WAIT(1);
        } else {
            CP_WAIT(0);
        }
        __syncthreads();

        const uint32_t sKh = sb + AK_BASE + cur * A_STG;
        const uint32_t sKl = sKh + A_HALF;
        const uint32_t sVh = sb + AV_BASE + cur * A_STG;
        const uint32_t sVl = sVh + A_HALF;

        // ---- S = Q K^T ----
        float s[8][4];
#pragma unroll
        for (int i = 0; i < 8; i++)
#pragma unroll
            for (int j = 0; j < 4; j++) s[i][j] = 0.0f;

#pragma unroll
        for (int ks = 0; ks < 4; ks++) {
            uint32_t aqh[4], aql[4];
            LDSM_X4(aqh[0], aqh[1], aqh[2], aqh[3], sb + AQ_H + a_off + ks * 32);
            LDSM_X4(aql[0], aql[1], aql[2], aql[3], sb + AQ_L + a_off + ks * 32);
#pragma unroll
            for (int p = 0; p < 4; p++) {
                uint32_t kh[4], kl[4];
                uint32_t off = k_off + (uint32_t)(p * 16 * SQ) * 2 + ks * 32;
                LDSM_X4(kh[0], kh[1], kh[2], kh[3], sKh + off);
                LDSM_X4(kl[0], kl[1], kl[2], kl[3], sKl + off);
                uint32_t bh0[2] = { kh[0], kh[1] }, bh1[2] = { kh[2], kh[3] };
                uint32_t bl0[2] = { kl[0], kl[1] }, bl1[2] = { kl[2], kl[3] };
                mma_bf16(s[2*p],   aqh, bh0);
                mma_bf16(s[2*p],   aqh, bl0);
                mma_bf16(s[2*p],   aql, bh0);
                mma_bf16(s[2*p+1], aqh, bh1);
                mma_bf16(s[2*p+1], aqh, bl1);
                mma_bf16(s[2*p+1], aql, bh1);
            }
        }

        // ---- online softmax (rows: l/4 -> c0,c1 ; l/4+8 -> c2,c3) ----
        float mx0 = -1e30f, mx1 = -1e30f;
#pragma unroll
        for (int ni = 0; ni < 8; ni++) {
            mx0 = fmaxf(mx0, fmaxf(s[ni][0], s[ni][1]));
            mx1 = fmaxf(mx1, fmaxf(s[ni][2], s[ni][3]));
        }
        mx0 = fmaxf(mx0, __shfl_xor_sync(0xffffffffu, mx0, 1));
        mx0 = fmaxf(mx0, __shfl_xor_sync(0xffffffffu, mx0, 2));
        mx1 = fmaxf(mx1, __shfl_xor_sync(0xffffffffu, mx1, 1));
        mx1 = fmaxf(mx1, __shfl_xor_sync(0xffffffffu, mx1, 2));

        float nm0 = fmaxf(m0, mx0), nm1 = fmaxf(m1, mx1);
        float al0 = __expf(m0 - nm0), al1 = __expf(m1 - nm1);
        float sum0 = 0.0f, sum1 = 0.0f;
#pragma unroll
        for (int ni = 0; ni < 8; ni++) {
            s[ni][0] = __expf(s[ni][0] - nm0); sum0 += s[ni][0];
            s[ni][1] = __expf(s[ni][1] - nm0); sum0 += s[ni][1];
            s[ni][2] = __expf(s[ni][2] - nm1); sum1 += s[ni][2];
            s[ni][3] = __expf(s[ni][3] - nm1); sum1 += s[ni][3];
        }
        sum0 += __shfl_xor_sync(0xffffffffu, sum0, 1);
        sum0 += __shfl_xor_sync(0xffffffffu, sum0, 2);
        sum1 += __shfl_xor_sync(0xffffffffu, sum1, 1);
        sum1 += __shfl_xor_sync(0xffffffffu, sum1, 2);
        l0 = l0 * al0 + sum0; m0 = nm0;
        l1 = l1 * al1 + sum1; m1 = nm1;
#pragma unroll
        for (int nb = 0; nb < 8; nb++) {
            o[nb][0] *= al0; o[nb][1] *= al0;
            o[nb][2] *= al1; o[nb][3] *= al1;
        }

        // ---- pack P hi/lo into A-operand regs ----
        uint32_t ph[16], pl[16];
#pragma unroll
        for (int ni = 0; ni < 8; ni++) {
            split2(s[ni][0], s[ni][1], ph[2*ni],   pl[2*ni]);
            split2(s[ni][2], s[ni][3], ph[2*ni+1], pl[2*ni+1]);
        }

        // ---- O += P V ----
#pragma unroll
        for (int kk = 0; kk < 4; kk++) {
            uint32_t aph[4] = { ph[4*kk], ph[4*kk+1], ph[4*kk+2], ph[4*kk+3] };
            uint32_t apl[4] = { pl[4*kk], pl[4*kk+1], pl[4*kk+2], pl[4*kk+3] };
#pragma unroll
            for (int p = 0; p < 4; p++) {
                uint32_t vh[4], vl[4];
                uint32_t off = v_off + (uint32_t)(kk * 16 * SQ) * 2 + p * 32;
                LDSM_X4T(vh[0], vh[1], vh[2], vh[3], sVh + off);
                LDSM_X4T(vl[0], vl[1], vl[2], vl[3], sVl + off);
                uint32_t bh0[2] = { vh[0], vh[1] }, bh1[2] = { vh[2], vh[3] };
                uint32_t bl0[2] = { vl[0], vl[1] }, bl1[2] = { vl[2], vl[3] };
                mma_bf16(o[2*p],   aph, bh0);
                mma_bf16(o[2*p],   aph, bl0);
                mma_bf16(o[2*p],   apl, bh0);
                mma_bf16(o[2*p+1], aph, bh1);
                mma_bf16(o[2*p+1], aph, bl1);
                mma_bf16(o[2*p+1], apl, bh1);
            }
        }
        __syncthreads();
    }

    // ---- epilogue: normalize, split to bf16 hi/lo ----
    const float inv0 = 1.0f / l0, inv1 = 1.0f / l1;
    const int r0 = w * 16 + (lane >> 2);
    const size_t base0 = (qrow + r0) * NCOLS + colb + (lane & 3) * 2;
    const size_t base1 = (qrow + r0 + 8) * NCOLS + colb + (lane & 3) * 2;
#pragma unroll
    for (int nb = 0; nb < 8; nb++) {
        uint32_t hh, ll;
        split2(o[nb][0] * inv0, o[nb][1] * inv0, hh, ll);
        *reinterpret_cast<uint32_t*>(&Oh_[base0 + nb * 8]) = hh;
        *reinterpret_cast<uint32_t*>(&Ol_[base0 + nb * 8]) = ll;
        split2(o[nb][2] * inv1, o[nb][3] * inv1, hh, ll);
        *reinterpret_cast<uint32_t*>(&Oh_[base1 + nb * 8]) = hh;
        *reinterpret_cast<uint32_t*>(&Ol_[base1 + nb * 8]) = ll;
    }
}

// ---------------------------------------------------------------------------
// Launch.  Inputs (metadata order): x, Wq, Wk, Wv, Wo, bo
// ---------------------------------------------------------------------------
extern "C" void kernel_launch(void* const* d_in, const int* in_sizes, int n_in,
                              void* d_out, int out_size) {
    const float* x  = (const float*)d_in[0];
    const float* Wq = (const float*)d_in[1];
    const float* Wk = (const float*)d_in[2];
    const float* Wv = (const float*)d_in[3];
    const float* Wo = (const float*)d_in[4];
    const float* bo = (const float*)d_in[5];
    float* out = (float*)d_out;

    __nv_bfloat16 *ah, *al, *bth, *btl, *qh, *ql, *kh, *kl, *vh, *vl;
    cudaGetSymbolAddress((void**)&ah, g_ah);
    cudaGetSymbolAddress((void**)&al, g_al);
    cudaGetSymbolAddress((void**)&bth, g_bth);
    cudaGetSymbolAddress((void**)&btl, g_btl);
    cudaGetSymbolAddress((void**)&qh, g_qh);
    cudaGetSymbolAddress((void**)&ql, g_ql);
    cudaGetSymbolAddress((void**)&kh, g_kh);
    cudaGetSymbolAddress((void**)&kl, g_kl);
    cudaGetSymbolAddress((void**)&vh, g_vh);
    cudaGetSymbolAddress((void**)&vl, g_vl);

    cudaFuncSetAttribute(gemm_mma, cudaFuncAttributeMaxDynamicSharedMemorySize, GSM_TOTAL);
    cudaFuncSetAttribute(attn_mma, cudaFuncAttributeMaxDynamicSharedMemorySize, A_SMEM);

    const int n4x = MROWS * KDIM / 4;
    dim3 tgrid(NCOLS / 32, KDIM / 32), tblock(32, 8);
    dim3 ggrid(NCOLS / 128, MROWS / 128);   // (8, 32)

    // x -> bf16 hi/lo
    split_kernel<<<(n4x + 255) / 256, 256>>>(x, ah, al, n4x);

    // QKV projections -> bf16 hi/lo outputs (Q pre-scaled by 1/8)
    tsplit_kernel<<<tgrid, tblock>>>(Wq, bth, btl);
    gemm_mma<<<ggrid, 256, GSM_TOTAL>>>(ah, al, bth, btl, nullptr, nullptr, qh, ql, ATT_SCALE);
    tsplit_kernel<<<tgrid, tblock>>>(Wk, bth, btl);
    gemm_mma<<<ggrid, 256, GSM_TOTAL>>>(ah, al, bth, btl, nullptr, nullptr, kh, kl, 1.0f);
    tsplit_kernel<<<tgrid, tblock>>>(Wv, bth, btl);
    gemm_mma<<<ggrid, 256, GSM_TOTAL>>>(ah, al, bth, btl, nullptr, nullptr, vh, vl, 1.0f);

    // MMA flash attention -> O hi/lo (reuses ah/al as the next GEMM's A)
    dim3 agrid(SEQ / 128, BS * NH);          // (16, 32)
    attn_mma<<<agrid, 256, A_SMEM>>>(qh, ql, kh, kl, vh, vl, ah, al);

    // Output projection + bias (fp32 out)
    tsplit_kernel<<<tgrid, tblock>>>(Wo, bth, btl);
    gemm_mma<<<ggrid, 256, GSM_TOTAL>>>(ah, al, bth, btl, out, bo, nullptr, nullptr, 1.0f);
}